// round 1
// baseline (speedup 1.0000x reference)
#include <cuda_runtime.h>
#include <stdint.h>

// Problem constants
#define Bn      64
#define Cn      2
#define Ln      64
#define Nn      16
#define NBINS   256            // Nn*Nn
#define VOX     (Ln*Ln*Ln)     // 262144
#define NBC     (Bn*Cn)        // 128

#define THREADS 256
#define VPT     4              // voxels per thread (one float4 load)
#define CHUNK   (THREADS*VPT)  // 1024 voxels per block
#define NCHUNKS (VOX/CHUNK)    // 256
#define BCGROUPS 4
#define BC_PER  (NBC/BCGROUPS) // 32

// Scratch for the binned sums g[b, c, bin]  (128 KB) — zeroed each launch.
__device__ float g_scratch[NBC * NBINS];

__global__ void zero_kernel() {
    int i = blockIdx.x * blockDim.x + threadIdx.x;
    if (i < NBC * NBINS) g_scratch[i] = 0.0f;
}

// Main accumulation: each block = (voxel chunk, bc group).
// Prologue computes the mag/bin table + warp match masks once per chunk,
// then streams x for 32 (b,c) rows with warp-aggregated fixed-point REDUX
// and leader-only global atomicAdd (REDG).
__global__ void __launch_bounds__(THREADS) accum_kernel(const float* __restrict__ x) {
    const int chunk = blockIdx.x;
    const int grp   = blockIdx.y;
    const int lane  = threadIdx.x & 31;
    const int base_v = chunk * CHUNK + threadIdx.x * VPT;

    int      ibin[VPT];
    int      imag[VPT];
    unsigned msk [VPT];
    bool     lead[VPT];

    #pragma unroll
    for (int j = 0; j < VPT; j++) {
        int v = base_v + j;
        float fi = (float)(v >> 12);
        float fj = (float)((v >> 6) & 63);
        float fk = (float)(v & 63);
        float mag = sqrtf(fi*fi + fj*fj + fk*fk);
        float xc  = sqrtf(fj*fj + fk*fk);
        float zc  = sqrtf(fj*fj + fi*fi);
        const float DEG = 57.29577951308232f;   // 180/pi (f32, as in reference)
        int ax = (int)floorf(atan2f(xc, fi) * DEG / 22.0f);
        int az = (int)floorf(atan2f(fk, zc) * DEG / 22.0f);
        ibin[j] = ax * Nn + az;
        imag[j] = __float2int_rn(mag * 65536.0f);      // 16.16 fixed point
        msk [j] = __match_any_sync(0xffffffffu, ibin[j]);
        lead[j] = (lane == (__ffs(msk[j]) - 1));
    }

    const int bc0 = grp * BC_PER;
    #pragma unroll 1
    for (int bc = bc0; bc < bc0 + BC_PER; bc++) {
        const float4 xv = __ldcs((const float4*)(x + (size_t)bc * VOX + base_v));
        float* grow = g_scratch + bc * NBINS;
        unsigned xu[4] = { __float_as_uint(xv.x), __float_as_uint(xv.y),
                           __float_as_uint(xv.z), __float_as_uint(xv.w) };
        #pragma unroll
        for (int j = 0; j < VPT; j++) {
            // x is exactly 0.0f or 1.0f: 0x3F800000 >> 29 == 1, 0 >> 29 == 0
            int s = imag[j] * (int)(xu[j] >> 29);
            int tot = __reduce_add_sync(msk[j], s);
            if (lead[j])
                atomicAdd(grow + ibin[j], (float)tot * 0x1p-16f);
        }
    }
}

// Per-channel group-norm over (B, N, N) = 16384 values, then affine + write out.
__global__ void norm_kernel(const float* __restrict__ gamma,
                            const float* __restrict__ beta,
                            float* __restrict__ out) {
    const int c   = blockIdx.x;
    const int tid = threadIdx.x;
    const int M   = Bn * NBINS;   // 16384

    double s = 0.0, s2 = 0.0;
    for (int idx = tid; idx < M; idx += THREADS) {
        int b = idx >> 8, n = idx & 255;
        float v = g_scratch[(b * Cn + c) * NBINS + n];
        s  += (double)v;
        s2 += (double)v * (double)v;
    }

    __shared__ double ssum[THREADS], ssq[THREADS];
    __shared__ float f_scale, f_shift;
    ssum[tid] = s; ssq[tid] = s2;
    __syncthreads();
    for (int o = THREADS / 2; o > 0; o >>= 1) {
        if (tid < o) { ssum[tid] += ssum[tid + o]; ssq[tid] += ssq[tid + o]; }
        __syncthreads();
    }
    if (tid == 0) {
        double mean = ssum[0] / (double)M;
        double var  = ssq[0] / (double)M - mean * mean;
        double rs   = 1.0 / sqrt(var + 1e-5);
        float scale = (float)rs * gamma[c];
        f_scale = scale;
        f_shift = beta[c] - (float)mean * scale;
    }
    __syncthreads();
    float scale = f_scale, shift = f_shift;

    for (int idx = tid; idx < M; idx += THREADS) {
        int b = idx >> 8, n = idx & 255;
        int off = (b * Cn + c) * NBINS + n;
        out[off] = g_scratch[off] * scale + shift;
    }
}

extern "C" void kernel_launch(void* const* d_in, const int* in_sizes, int n_in,
                              void* d_out, int out_size) {
    const float* x     = (const float*)d_in[0];
    const float* gamma = (const float*)d_in[1];
    const float* beta  = (const float*)d_in[2];
    float* out = (float*)d_out;

    zero_kernel<<<(NBC * NBINS + 255) / 256, 256>>>();
    dim3 grid(NCHUNKS, BCGROUPS);
    accum_kernel<<<grid, THREADS>>>(x);
    norm_kernel<<<Cn, THREADS>>>(gamma, beta, out);
}

// round 2
// speedup vs baseline: 1.0691x; 1.0691x over previous
#include <cuda_runtime.h>
#include <stdint.h>

// Problem constants
#define Bn      64
#define Cn      2
#define Ln      64
#define Nn      16
#define NBINS   256            // Nn*Nn
#define VOX     (Ln*Ln*Ln)     // 262144
#define NBC     (Bn*Cn)        // 128

#define THREADS 256
#define VPT     4              // voxels per thread (one float4 load)
#define CHUNK   (THREADS*VPT)  // 1024 voxels per block
#define NCHUNKS (VOX/CHUNK)    // 256
#define BCGROUPS 4
#define BC_PER  (NBC/BCGROUPS) // 32

#define FXS     8192.0f        // fixed-point scale (2^13)

// Scratch for the binned sums g[b, c, bin]  (128 KB) — zeroed each launch.
__device__ float g_scratch[NBC * NBINS];

__global__ void zero_kernel() {
    int i = blockIdx.x * blockDim.x + threadIdx.x;
    if (i < NBC * NBINS) g_scratch[i] = 0.0f;
}

// Main accumulation: block = (voxel chunk, bc group of 32 rows).
// Prologue computes the bin table + warp match masks once per chunk.
// Body streams two bc rows per iteration (MLP=2), warp-aggregates with
// REDUX in 2^13 fixed point, leaders deposit to a shared-memory block
// histogram. Epilogue flushes nonzero bins with one global atomic each.
__global__ void __launch_bounds__(THREADS) accum_kernel(const float* __restrict__ x) {
    __shared__ int hist[BC_PER][NBINS];   // 32 KB

    const int chunk = blockIdx.x;
    const int grp   = blockIdx.y;
    const int lane  = threadIdx.x & 31;
    const int base_v = chunk * CHUNK + threadIdx.x * VPT;

    // Zero shared histogram
    for (int i = threadIdx.x; i < BC_PER * NBINS; i += THREADS)
        ((int*)hist)[i] = 0;

    int      ibin[VPT];
    int      imag[VPT];
    unsigned msk [VPT];
    bool     lead[VPT];

    #pragma unroll
    for (int j = 0; j < VPT; j++) {
        int v = base_v + j;
        float fi = (float)(v >> 12);
        float fj = (float)((v >> 6) & 63);
        float fk = (float)(v & 63);
        float mag = sqrtf(fi*fi + fj*fj + fk*fk);
        float xc  = sqrtf(fj*fj + fk*fk);
        float zc  = sqrtf(fj*fj + fi*fi);
        const float DEG = 57.29577951308232f;   // 180/pi
        int ax = (int)floorf(atan2f(xc, fi) * DEG / 22.0f);
        int az = (int)floorf(atan2f(fk, zc) * DEG / 22.0f);
        ibin[j] = ax * Nn + az;
        imag[j] = __float2int_rn(mag * FXS);
        msk [j] = __match_any_sync(0xffffffffu, ibin[j]);
        lead[j] = (lane == (__ffs(msk[j]) - 1));
    }
    __syncthreads();

    const int bc0 = grp * BC_PER;
    const float* xb = x + base_v;

    #pragma unroll 1
    for (int bb = 0; bb < BC_PER / 2; bb++) {
        const int rA = bb;
        const int rB = bb + BC_PER / 2;
        // Two independent streaming loads in flight before any dependent work.
        const float4 vA = __ldcs((const float4*)(xb + (size_t)(bc0 + rA) * VOX));
        const float4 vB = __ldcs((const float4*)(xb + (size_t)(bc0 + rB) * VOX));

        unsigned uA[4] = { __float_as_uint(vA.x), __float_as_uint(vA.y),
                           __float_as_uint(vA.z), __float_as_uint(vA.w) };
        unsigned uB[4] = { __float_as_uint(vB.x), __float_as_uint(vB.y),
                           __float_as_uint(vB.z), __float_as_uint(vB.w) };

        #pragma unroll
        for (int j = 0; j < VPT; j++) {
            // x is exactly 0.0f or 1.0f: 0x3F800000 >> 29 == 1, 0 >> 29 == 0
            int sA = imag[j] * (int)(uA[j] >> 29);
            int sB = imag[j] * (int)(uB[j] >> 29);
            int tA = __reduce_add_sync(msk[j], sA);
            int tB = __reduce_add_sync(msk[j], sB);
            if (lead[j]) {
                atomicAdd(&hist[rA][ibin[j]], tA);
                atomicAdd(&hist[rB][ibin[j]], tB);
            }
        }
    }
    __syncthreads();

    // Flush block histogram: only nonzero bins hit global memory.
    for (int idx = threadIdx.x; idx < BC_PER * NBINS; idx += THREADS) {
        int r   = idx >> 8;
        int bin = idx & 255;
        int v   = hist[r][bin];
        if (v)
            atomicAdd(&g_scratch[(bc0 + r) * NBINS + bin], (float)v * (1.0f / FXS));
    }
}

// Per-channel group-norm over (B, N, N) = 16384 values, then affine + write out.
#define NTHR 1024
__global__ void norm_kernel(const float* __restrict__ gamma,
                            const float* __restrict__ beta,
                            float* __restrict__ out) {
    const int c   = blockIdx.x;
    const int tid = threadIdx.x;
    const int M   = Bn * NBINS;   // 16384

    double s = 0.0, s2 = 0.0;
    for (int idx = tid; idx < M; idx += NTHR) {
        int b = idx >> 8, n = idx & 255;
        float v = g_scratch[(b * Cn + c) * NBINS + n];
        s  += (double)v;
        s2 += (double)v * (double)v;
    }

    __shared__ double ssum[NTHR], ssq[NTHR];
    __shared__ float f_scale, f_shift;
    ssum[tid] = s; ssq[tid] = s2;
    __syncthreads();
    for (int o = NTHR / 2; o > 0; o >>= 1) {
        if (tid < o) { ssum[tid] += ssum[tid + o]; ssq[tid] += ssq[tid + o]; }
        __syncthreads();
    }
    if (tid == 0) {
        double mean = ssum[0] / (double)M;
        double var  = ssq[0] / (double)M - mean * mean;
        double rs   = 1.0 / sqrt(var + 1e-5);
        float scale = (float)rs * gamma[c];
        f_scale = scale;
        f_shift = beta[c] - (float)mean * scale;
    }
    __syncthreads();
    float scale = f_scale, shift = f_shift;

    for (int idx = tid; idx < M; idx += NTHR) {
        int b = idx >> 8, n = idx & 255;
        int off = (b * Cn + c) * NBINS + n;
        out[off] = g_scratch[off] * scale + shift;
    }
}

extern "C" void kernel_launch(void* const* d_in, const int* in_sizes, int n_in,
                              void* d_out, int out_size) {
    const float* x     = (const float*)d_in[0];
    const float* gamma = (const float*)d_in[1];
    const float* beta  = (const float*)d_in[2];
    float* out = (float*)d_out;

    zero_kernel<<<(NBC * NBINS + 255) / 256, 256>>>();
    dim3 grid(NCHUNKS, BCGROUPS);
    accum_kernel<<<grid, THREADS>>>(x);
    norm_kernel<<<Cn, NTHR>>>(gamma, beta, out);
}

// round 4
// speedup vs baseline: 1.2045x; 1.1267x over previous
#include <cuda_runtime.h>
#include <stdint.h>

// Problem constants
#define Bn      64
#define Cn      2
#define Nn      16
#define NBINS   256            // Nn*Nn
#define VOX     262144         // 64^3
#define NBC     (Bn*Cn)        // 128

#define THREADS 256
#define VPT     16             // voxels per thread (4x float4 per row)
#define CHUNK   (THREADS*VPT)  // 4096 voxels per block
#define NCHUNKS (VOX/CHUNK)    // 64
#define BCGROUPS 8
#define BC_PER  (NBC/BCGROUPS) // 16

// Binned sums g[b, c, bin] (128 KB). Zero-initialized at module load;
// norm_kernel re-zeroes it after reading, so the invariant
// "g_scratch == 0 on entry to kernel_launch" holds across graph replays.
__device__ float g_scratch[NBC * NBINS];

// Accumulation: block = (4096-voxel chunk, group of 16 bc rows).
// Key structure: along k, bin = ax*16+az is monotone non-decreasing, so each
// thread's 16 consecutive voxels form a few contiguous equal-bin segments.
// Prologue computes mag[16], a boundary bitmask, and flush byte-offsets once.
// Per row the element work is ONE serial FFMA; deposits are rare predicated
// shared-float atomics at segment boundaries. No REDUX, no per-element MIO.
__global__ void __launch_bounds__(THREADS, 3) accum_kernel(const float* __restrict__ x) {
    __shared__ float hist[BC_PER][NBINS];   // 16 KB

    const int chunk  = blockIdx.x;
    const int grp    = blockIdx.y;
    const int base_v = chunk * CHUNK + threadIdx.x * VPT;

    for (int i = threadIdx.x; i < BC_PER * NBINS; i += THREADS)
        ((float*)hist)[i] = 0.0f;

    float    mag[VPT];
    int      off[VPT];     // flush target byte-offset (bin[e-1]*4), valid for e>=1
    unsigned fmask = 0;    // bit e set => bin changes at element e
    int      prevbin = 0;

    #pragma unroll
    for (int e = 0; e < VPT; e++) {
        int v = base_v + e;
        float fi = (float)(v >> 12);
        float fj = (float)((v >> 6) & 63);
        float fk = (float)(v & 63);
        mag[e] = sqrtf(fi*fi + fj*fj + fk*fk);
        float xc = sqrtf(fj*fj + fk*fk);
        float zc = sqrtf(fj*fj + fi*fi);
        const float DEG = 57.29577951308232f;   // 180/pi
        int ax = (int)floorf(atan2f(xc, fi) * DEG / 22.0f);
        int az = (int)floorf(atan2f(fk, zc) * DEG / 22.0f);
        int bin = ax * Nn + az;
        if (e > 0 && bin != prevbin) fmask |= (1u << e);
        off[e] = prevbin * 4;
        prevbin = bin;
    }
    const int lastoff = prevbin * 4;
    __syncthreads();

    const int bc0 = grp * BC_PER;
    const float* xb = x + base_v;

    #pragma unroll 1
    for (int r = 0; r < BC_PER; r++) {
        const float4* p = (const float4*)(xb + (size_t)(bc0 + r) * VOX);
        float4 v0 = __ldcs(p + 0);
        float4 v1 = __ldcs(p + 1);
        float4 v2 = __ldcs(p + 2);
        float4 v3 = __ldcs(p + 3);
        float xv[VPT] = { v0.x, v0.y, v0.z, v0.w,  v1.x, v1.y, v1.z, v1.w,
                          v2.x, v2.y, v2.z, v2.w,  v3.x, v3.y, v3.z, v3.w };
        char* rowhist = (char*)hist[r];

        // x is exactly 0.0f or 1.0f -> direct FFMA, no unpack.
        float run = xv[0] * mag[0];
        #pragma unroll
        for (int e = 1; e < VPT; e++) {
            bool f = (fmask >> e) & 1u;
            if (f) atomicAdd((float*)(rowhist + off[e]), run);   // @P ATOMS
            run = fmaf(xv[e], mag[e], f ? 0.0f : run);
        }
        atomicAdd((float*)(rowhist + lastoff), run);
    }
    __syncthreads();

    // Flush nonzero bins to global.
    for (int idx = threadIdx.x; idx < BC_PER * NBINS; idx += THREADS) {
        float v = ((float*)hist)[idx];
        if (v != 0.0f)
            atomicAdd(&g_scratch[(bc0 + (idx >> 8)) * NBINS + (idx & 255)], v);
    }
}

// Per-channel group-norm over (B, N, N) = 16384 values, affine, write out,
// then re-zero g_scratch for the next replay.
#define NTHR 1024
__global__ void norm_kernel(const float* __restrict__ gamma,
                            const float* __restrict__ beta,
                            float* __restrict__ out) {
    const int c   = blockIdx.x;
    const int tid = threadIdx.x;
    const int M   = Bn * NBINS;   // 16384

    double s = 0.0, s2 = 0.0;
    for (int idx = tid; idx < M; idx += NTHR) {
        int b = idx >> 8, n = idx & 255;
        float v = g_scratch[(b * Cn + c) * NBINS + n];
        s  += (double)v;
        s2 += (double)v * (double)v;
    }

    __shared__ double ssum[NTHR], ssq[NTHR];
    __shared__ float f_scale, f_shift;
    ssum[tid] = s; ssq[tid] = s2;
    __syncthreads();
    for (int o = NTHR / 2; o > 0; o >>= 1) {
        if (tid < o) { ssum[tid] += ssum[tid + o]; ssq[tid] += ssq[tid + o]; }
        __syncthreads();
    }
    if (tid == 0) {
        double mean = ssum[0] / (double)M;
        double var  = ssq[0] / (double)M - mean * mean;
        double rs   = 1.0 / sqrt(var + 1e-5);
        float scale = (float)rs * gamma[c];
        f_scale = scale;
        f_shift = beta[c] - (float)mean * scale;
    }
    __syncthreads();
    float scale = f_scale, shift = f_shift;

    for (int idx = tid; idx < M; idx += NTHR) {
        int b = idx >> 8, n = idx & 255;
        int off = (b * Cn + c) * NBINS + n;
        out[off] = g_scratch[off] * scale + shift;
        g_scratch[off] = 0.0f;   // restore invariant for next graph replay
    }
}

extern "C" void kernel_launch(void* const* d_in, const int* in_sizes, int n_in,
                              void* d_out, int out_size) {
    const float* x     = (const float*)d_in[0];
    const float* gamma = (const float*)d_in[1];
    const float* beta  = (const float*)d_in[2];
    float* out = (float*)d_out;

    dim3 grid(NCHUNKS, BCGROUPS);
    accum_kernel<<<grid, THREADS>>>(x);
    norm_kernel<<<Cn, NTHR>>>(gamma, beta, out);
}

// round 5
// speedup vs baseline: 1.4666x; 1.2176x over previous
#include <cuda_runtime.h>
#include <stdint.h>

#define Bn 64
#define Cn 2
#define Nn 16
#define NBINS 256
#define VOX 262144
#define NBC 128

#define THREADS 256
#define BCG 32                 // bc rows per block (lane <-> bc)
#define NBCG 4
#define CHUNK 2048             // voxels per block = 32 j-lines
#define NCHUNK 128             // VOX / CHUNK
#define VOXT 256               // voxels per tile step (8 half-lines)
#define STEPS 8                // CHUNK / VOXT
#define XSTRIDE 258            // floats per bc row in xs (8B-aligned, 2-way bank conflict)
#define CBINS 25               // ax,az in 0..4 -> compact bin = ax*5+az
#define HSTRIDE 33             // hist row stride -> bank (lane+cb)%32, conflict-free
#define MAXSEG 12

#define XSBUF_F (BCG*XSTRIDE)          // 8256 floats / buffer
#define HIST_F  (8*BCG*HSTRIDE)        // 8448 floats
#define NHALF   (CHUNK/32)             // 64 half-lines / chunk
#define SMEM_BYTES (2*XSBUF_F*4 + HIST_F*4 + NHALF*4 + NHALF*MAXSEG)

__device__ float g_scratch[NBC * NBINS];   // zero at load; norm re-zeroes each launch

__device__ __forceinline__ void stage(const float* __restrict__ x, int bc0, int v0,
                                      float* dst, int tid) {
    #pragma unroll
    for (int i = 0; i < 16; i++) {
        int lin = tid + i * THREADS;       // 0..4095 : 8B units
        int row = lin >> 7;                // 32 rows x 128 units
        int u   = lin & 127;
        const float* g = x + (size_t)(bc0 + row) * VOX + v0 + u * 2;
        unsigned s = (unsigned)__cvta_generic_to_shared(dst + row * XSTRIDE + u * 2);
        asm volatile("cp.async.ca.shared.global [%0], [%1], 8;\n" :: "r"(s), "l"(g));
    }
}

// One warp processes one half-line (32 k) for 32 bc rows (lane = bc).
// mask/segbins are warp-uniform; deposits are conflict-free non-atomic SMEM RMW.
template<int K0>
__device__ __forceinline__ void process_half(const float* __restrict__ xrow,
                                             float c0, unsigned mask,
                                             const unsigned char* __restrict__ sb,
                                             float* __restrict__ hrow) {
    float run = 0.f;
    #pragma unroll
    for (int k = 0; k < 32; k++) {
        if (k > 0 && ((mask >> k) & 1u)) {          // warp-uniform branch
            int cb = sb[__popc(mask & ((1u << k) - 1u))];
            hrow[cb] += run;                        // LDS+FADD+STS, lane-distinct rows
            run = 0.f;
        }
        float fk = (float)(K0 + k);                 // compile-time literal
        float m = sqrtf(fmaf(fk, fk, c0));
        run = fmaf(xrow[k], m, run);
    }
    hrow[sb[__popc(mask)]] += run;
}

__global__ void __launch_bounds__(THREADS) accum_kernel(const float* __restrict__ x) {
    extern __shared__ float sm[];
    float* xs   = sm;                                  // 2 * XSBUF_F
    float* hist = sm + 2 * XSBUF_F;                    // HIST_F
    unsigned* masks = (unsigned*)(hist + HIST_F);      // NHALF
    unsigned char* segb = (unsigned char*)(masks + NHALF);

    const int tid  = threadIdx.x;
    const int w    = tid >> 5, lane = tid & 31;
    const int chunk0 = blockIdx.x * CHUNK;
    const int bc0    = blockIdx.y * BCG;

    // Prefetch tile 0 while we compute bin geometry.
    stage(x, bc0, chunk0, xs, tid);
    asm volatile("cp.async.commit_group;\n" ::: "memory");

    // Bin geometry (per-chunk, bc-independent). binb temporarily lives in hist.
    unsigned char* binb = (unsigned char*)hist;
    #pragma unroll
    for (int i2 = 0; i2 < CHUNK / THREADS; i2++) {
        int lv = tid + i2 * THREADS;
        int v = chunk0 + lv;
        float fi = (float)(v >> 12);
        float fj = (float)((v >> 6) & 63);
        float fk = (float)(v & 63);
        float xc = sqrtf(fj * fj + fk * fk);
        float zc = sqrtf(fj * fj + fi * fi);
        const float DEG = 57.29577951308232f;   // 180/pi
        int ax = (int)floorf(atan2f(xc, fi) * DEG / 22.0f);
        int az = (int)floorf(atan2f(fk, zc) * DEG / 22.0f);
        binb[lv] = (unsigned char)(ax * 5 + az);
    }
    __syncthreads();

    // Build per-half-line boundary mask + segment-bin list.
    if (tid < NHALF) {
        int base = tid * 32;
        unsigned mask = 0;
        unsigned char prev = binb[base];
        unsigned char* s = segb + tid * MAXSEG;
        s[0] = prev;
        int ns = 1;
        for (int k = 1; k < 32; k++) {
            unsigned char b = binb[base + k];
            if (b != prev) { mask |= 1u << k; s[ns++] = b; prev = b; }
        }
        masks[tid] = mask;
    }
    __syncthreads();
    for (int i2 = tid; i2 < HIST_F; i2 += THREADS) hist[i2] = 0.f;   // binb dead now
    __syncthreads();

    float* hrow = hist + (w * BCG + lane) * HSTRIDE;

    #pragma unroll 1
    for (int s = 0; s < STEPS; s++) {
        if (s + 1 < STEPS) {
            stage(x, bc0, chunk0 + (s + 1) * VOXT, xs + ((s + 1) & 1) * XSBUF_F, tid);
            asm volatile("cp.async.commit_group;\n" ::: "memory");
            asm volatile("cp.async.wait_group 1;\n" ::: "memory");
        } else {
            asm volatile("cp.async.wait_group 0;\n" ::: "memory");
        }
        __syncthreads();

        const int h = s * 8 + w;                 // half-line index in chunk
        const int v0 = chunk0 + h * 32;
        const float fi = (float)(v0 >> 12);
        const float fj = (float)((v0 >> 6) & 63);
        const float c0 = fi * fi + fj * fj;
        const float* xrow = xs + (s & 1) * XSBUF_F + lane * XSTRIDE + w * 32;
        const unsigned mask = masks[h];
        const unsigned char* sb = segb + h * MAXSEG;

        if (w & 1) process_half<32>(xrow, c0, mask, sb, hrow);
        else       process_half<0 >(xrow, c0, mask, sb, hrow);
        __syncthreads();
    }

    // Reduce the 8 per-warp histograms and flush to global (25 live bins x 32 bc).
    for (int idx = tid; idx < BCG * CBINS; idx += THREADS) {
        int bcl = idx / CBINS;
        int cb  = idx - bcl * CBINS;
        float s = 0.f;
        #pragma unroll
        for (int w2 = 0; w2 < 8; w2++) s += hist[(w2 * BCG + bcl) * HSTRIDE + cb];
        int ax = cb / 5;
        int bin = ax * Nn + (cb - ax * 5);
        if (s != 0.f) atomicAdd(&g_scratch[(bc0 + bcl) * NBINS + bin], s);
    }
}

// Per-channel norm over (B,N,N)=16384 values: fp32 two-pass + shuffle reduction.
__global__ void norm_kernel(const float* __restrict__ gamma,
                            const float* __restrict__ beta,
                            float* __restrict__ out) {
    const int c = blockIdx.x, tid = threadIdx.x;
    const int M = Bn * NBINS;
    __shared__ float red[8];
    __shared__ float sh_mean, sh_scale, sh_shift;

    float s = 0.f;
    for (int idx = tid; idx < M; idx += THREADS) {
        int b = idx >> 8, n = idx & 255;
        s += g_scratch[(b * Cn + c) * NBINS + n];
    }
    #pragma unroll
    for (int o = 16; o; o >>= 1) s += __shfl_down_sync(0xffffffffu, s, o);
    if ((tid & 31) == 0) red[tid >> 5] = s;
    __syncthreads();
    if (tid == 0) {
        float t = 0.f;
        #pragma unroll
        for (int i = 0; i < 8; i++) t += red[i];
        sh_mean = t / (float)M;
    }
    __syncthreads();
    const float mean = sh_mean;

    float s2 = 0.f;
    for (int idx = tid; idx < M; idx += THREADS) {
        int b = idx >> 8, n = idx & 255;
        float d = g_scratch[(b * Cn + c) * NBINS + n] - mean;
        s2 += d * d;
    }
    __syncthreads();
    #pragma unroll
    for (int o = 16; o; o >>= 1) s2 += __shfl_down_sync(0xffffffffu, s2, o);
    if ((tid & 31) == 0) red[tid >> 5] = s2;
    __syncthreads();
    if (tid == 0) {
        float t = 0.f;
        #pragma unroll
        for (int i = 0; i < 8; i++) t += red[i];
        float var = t / (float)M;
        float sc = rsqrtf(var + 1e-5f) * gamma[c];
        sh_scale = sc;
        sh_shift = beta[c] - mean * sc;
    }
    __syncthreads();
    const float scale = sh_scale, shift = sh_shift;
    for (int idx = tid; idx < M; idx += THREADS) {
        int b = idx >> 8, n = idx & 255;
        int off = (b * Cn + c) * NBINS + n;
        out[off] = g_scratch[off] * scale + shift;
        g_scratch[off] = 0.f;   // restore zero-invariant for next graph replay
    }
}

extern "C" void kernel_launch(void* const* d_in, const int* in_sizes, int n_in,
                              void* d_out, int out_size) {
    const float* x     = (const float*)d_in[0];
    const float* gamma = (const float*)d_in[1];
    const float* beta  = (const float*)d_in[2];
    float* out = (float*)d_out;

    cudaFuncSetAttribute(accum_kernel,
                         cudaFuncAttributeMaxDynamicSharedMemorySize, SMEM_BYTES);
    dim3 grid(NCHUNK, NBCG);
    accum_kernel<<<grid, THREADS, SMEM_BYTES>>>(x);
    norm_kernel<<<Cn, THREADS>>>(gamma, beta, out);
}